// round 7
// baseline (speedup 1.0000x reference)
#include <cuda_runtime.h>
#include <cuda_bf16.h>

// Problem constants (fixed shapes from reference)
#define PHM      4
#define IN_FEATS 2048
#define OUT_FEATS 8192
#define TOKENS   8192
#define IN_PER   (IN_FEATS / PHM)    // 512
#define OUT_PER  (OUT_FEATS / PHM)   // 2048

// 64 MB scratch for the materialized H matrix (2048 x 8192, row-major).
// __device__ global array: allowed scratch (no dynamic allocation).
__device__ float g_H[(size_t)IN_FEATS * OUT_FEATS];

// ---------------------------------------------------------------------------
// Kernel 1: materialize H[r, col] = sum_i rule[i, a, k] * W[i, c, p]
//   r = a*IN_PER + c   (a in [0,4), c in [0,512))
//   col = k*OUT_PER + p (k in [0,4), p in [0,2048))
// One thread per float4 of H (4 consecutive p values, never crossing a k
// boundary since OUT_PER % 4 == 0).
// ---------------------------------------------------------------------------
__global__ __launch_bounds__(256) void build_H_kernel(
    const float* __restrict__ rule,   // (4,4,4)
    const float* __restrict__ W)      // (4,512,2048)
{
    const int idx = blockIdx.x * blockDim.x + threadIdx.x;
    const int ncols4 = OUT_FEATS / 4;
    if (idx >= IN_FEATS * ncols4) return;

    const int r   = idx / ncols4;
    const int col = (idx - r * ncols4) * 4;

    const int a = r >> 9;            // r / 512
    const int c = r & 511;           // r % 512
    const int k = col >> 11;         // col / 2048
    const int p = col & 2047;        // col % 2048

    float4 acc = make_float4(0.f, 0.f, 0.f, 0.f);
#pragma unroll
    for (int i = 0; i < PHM; i++) {
        const float s = __ldg(&rule[(i * PHM + a) * PHM + k]);
        const float4 w = *reinterpret_cast<const float4*>(
            &W[((size_t)(i * IN_PER + c)) * OUT_PER + p]);
        acc.x += s * w.x;
        acc.y += s * w.y;
        acc.z += s * w.z;
        acc.w += s * w.w;
    }
    *reinterpret_cast<float4*>(&g_H[(size_t)r * OUT_FEATS + col]) = acc;
}

// ---------------------------------------------------------------------------
// Kernel 2: y = x @ H + b   (8192 x 2048) @ (2048 x 8192)
// Classic 128x128x8 SGEMM, 256 threads, 8x8 accumulator per thread held as
// 2x2 chunks of 4 (rows {tr*4, tr*4+64}, cols {tc*4, tc*4+64}) so LDS.128
// reads are bank-conflict-free. As padded to 132 floats/row (528 B, still
// 16B-aligned per row) to kill STS conflicts on the transposed A store.
// ---------------------------------------------------------------------------
#define BM 128
#define BN 128
#define BK 8
#define ASTRIDE 132   // BM + 4 padding; 132*4 = 528 bytes, multiple of 16

__global__ __launch_bounds__(256) void sgemm_kernel(
    const float* __restrict__ A,      // x: (8192, 2048) row-major
    const float* __restrict__ bias,   // (8192,)
    float* __restrict__ C)            // y: (8192, 8192) row-major
{
    __shared__ __align__(16) float As[BK][ASTRIDE];
    __shared__ __align__(16) float Bs[BK][BN];

    const float* __restrict__ B = g_H;

    const int bx = blockIdx.x;   // N tile
    const int by = blockIdx.y;   // M tile
    const int tid = threadIdx.x;

    const int tr = tid >> 4;     // 0..15  (row group)
    const int tc = tid & 15;     // 0..15  (col group)

    // A tile loads: 128 rows x 8 cols -> one float4 per thread
    const int aRow = tid >> 1;          // 0..127
    const int aCol = (tid & 1) * 4;     // 0 or 4
    // B tile loads: 8 rows x 128 cols -> one float4 per thread
    const int bRow = tid >> 5;          // 0..7
    const int bCol = (tid & 31) * 4;    // 0..124

    const float* Ab = A + (size_t)(by * BM) * IN_FEATS;
    const float* Bb = B + bx * BN;

    float acc[8][8];
#pragma unroll
    for (int m = 0; m < 8; m++)
#pragma unroll
        for (int n = 0; n < 8; n++) acc[m][n] = 0.f;

    for (int k0 = 0; k0 < IN_FEATS; k0 += BK) {
        // Load + transpose A tile
        float4 av = *reinterpret_cast<const float4*>(
            &Ab[(size_t)aRow * IN_FEATS + k0 + aCol]);
        As[aCol + 0][aRow] = av.x;
        As[aCol + 1][aRow] = av.y;
        As[aCol + 2][aRow] = av.z;
        As[aCol + 3][aRow] = av.w;

        // Load B tile (rows contiguous)
        float4 bv = *reinterpret_cast<const float4*>(
            &Bb[(size_t)(k0 + bRow) * OUT_FEATS + bCol]);
        *reinterpret_cast<float4*>(&Bs[bRow][bCol]) = bv;

        __syncthreads();

#pragma unroll
        for (int kk = 0; kk < BK; kk++) {
            const float4 m0 = *reinterpret_cast<const float4*>(&As[kk][tr * 4]);
            const float4 m1 = *reinterpret_cast<const float4*>(&As[kk][tr * 4 + 64]);
            const float4 n0 = *reinterpret_cast<const float4*>(&Bs[kk][tc * 4]);
            const float4 n1 = *reinterpret_cast<const float4*>(&Bs[kk][tc * 4 + 64]);

            const float rm[8] = {m0.x, m0.y, m0.z, m0.w, m1.x, m1.y, m1.z, m1.w};
            const float rn[8] = {n0.x, n0.y, n0.z, n0.w, n1.x, n1.y, n1.z, n1.w};

#pragma unroll
            for (int m = 0; m < 8; m++)
#pragma unroll
                for (int n = 0; n < 8; n++)
                    acc[m][n] += rm[m] * rn[n];
        }
        __syncthreads();
    }

    // Epilogue: add bias, write out (coalesced float4 stores)
#pragma unroll
    for (int mc = 0; mc < 2; mc++) {
#pragma unroll
        for (int mi = 0; mi < 4; mi++) {
            const int m = mc * 4 + mi;
            const int row = by * BM + mc * 64 + tr * 4 + mi;
#pragma unroll
            for (int nc = 0; nc < 2; nc++) {
                const int col = bx * BN + nc * 64 + tc * 4;
                const float4 bb = *reinterpret_cast<const float4*>(&bias[col]);
                float4 o;
                o.x = acc[m][nc * 4 + 0] + bb.x;
                o.y = acc[m][nc * 4 + 1] + bb.y;
                o.z = acc[m][nc * 4 + 2] + bb.z;
                o.w = acc[m][nc * 4 + 3] + bb.w;
                *reinterpret_cast<float4*>(&C[(size_t)row * OUT_FEATS + col]) = o;
            }
        }
    }
}

// ---------------------------------------------------------------------------
// Launch: inputs per metadata order: x, phm_rule, W, b. Output float32.
// ---------------------------------------------------------------------------
extern "C" void kernel_launch(void* const* d_in, const int* in_sizes, int n_in,
                              void* d_out, int out_size) {
    const float* x    = (const float*)d_in[0];
    const float* rule = (const float*)d_in[1];
    const float* W    = (const float*)d_in[2];
    const float* b    = (const float*)d_in[3];
    float* y = (float*)d_out;

    (void)in_sizes; (void)n_in; (void)out_size;

    // Kernel 1: build H (16.7M elems, float4 per thread)
    {
        const int total4 = IN_FEATS * (OUT_FEATS / 4);
        const int threads = 256;
        const int blocks = (total4 + threads - 1) / threads;
        build_H_kernel<<<blocks, threads>>>(rule, W);
    }

    // Kernel 2: y = x @ H + b
    {
        dim3 grid(OUT_FEATS / BN, TOKENS / BM);   // (64, 64)
        sgemm_kernel<<<grid, 256>>>(x, b, y);
    }
}

// round 12
// speedup vs baseline: 2.8923x; 2.8923x over previous
#include <cuda_runtime.h>
#include <cuda_bf16.h>
#include <cstdint>

// ---------------------------------------------------------------------------
// Problem constants
// ---------------------------------------------------------------------------
#define PHM      4
#define IN_FEATS 2048
#define OUT_FEATS 8192
#define TOKENS   8192
#define IN_PER   (IN_FEATS / PHM)    // 512
#define OUT_PER  (OUT_FEATS / PHM)   // 2048

// ---------------------------------------------------------------------------
// Static device scratch (allowed; no dynamic allocation)
// ---------------------------------------------------------------------------
__device__ __nv_bfloat16 g_xhi[(size_t)TOKENS * IN_FEATS];
__device__ __nv_bfloat16 g_xlo[(size_t)TOKENS * IN_FEATS];
__device__ __nv_bfloat16 g_Hthi[(size_t)OUT_FEATS * IN_FEATS];  // H^T [n][k]
__device__ __nv_bfloat16 g_Htlo[(size_t)OUT_FEATS * IN_FEATS];

// ---------------------------------------------------------------------------
// Helpers (only non-arch-suffixed PTX: cp.async sm_80, ldmatrix sm_75,
// mma.sync bf16 sm_80 — all legal on plain compute_103)
// ---------------------------------------------------------------------------
__device__ __forceinline__ uint32_t smem_to_u32(const void* p) {
    uint32_t a;
    asm("{ .reg .u64 t; cvta.to.shared.u64 t, %1; cvt.u32.u64 %0, t; }"
        : "=r"(a) : "l"(p));
    return a;
}

#define SMEM_SWIZZLE_128B(o) ((o) ^ (((o) >> 3) & 0x70))

#define CP_ASYNC16(smem_addr, gptr) \
    asm volatile("cp.async.cg.shared.global [%0], [%1], 16;" \
                 :: "r"((uint32_t)(smem_addr)), "l"(gptr) : "memory")
#define CP_ASYNC_COMMIT() asm volatile("cp.async.commit_group;" ::: "memory")

#define LDSM_X4(r0, r1, r2, r3, addr) \
    asm volatile("ldmatrix.sync.aligned.m8n8.x4.shared.b16 {%0,%1,%2,%3}, [%4];" \
                 : "=r"(r0), "=r"(r1), "=r"(r2), "=r"(r3) : "r"(addr))

#define MMA_BF16(d, a, b0, b1) \
    asm volatile("mma.sync.aligned.m16n8k16.row.col.f32.bf16.bf16.f32 " \
                 "{%0,%1,%2,%3}, {%4,%5,%6,%7}, {%8,%9}, {%0,%1,%2,%3};" \
                 : "+f"((d)[0]), "+f"((d)[1]), "+f"((d)[2]), "+f"((d)[3]) \
                 : "r"((a)[0]), "r"((a)[1]), "r"((a)[2]), "r"((a)[3]), \
                   "r"(b0), "r"(b1))

// ---------------------------------------------------------------------------
// Kernel 1: split x into bf16 hi/lo
// ---------------------------------------------------------------------------
__global__ __launch_bounds__(256) void split_x_kernel(const float* __restrict__ x) {
    const size_t i = (size_t)blockIdx.x * 256 + threadIdx.x;  // float4 index
    const float4 v = reinterpret_cast<const float4*>(x)[i];

    __nv_bfloat16 h0 = __float2bfloat16(v.x);
    __nv_bfloat16 h1 = __float2bfloat16(v.y);
    __nv_bfloat16 h2 = __float2bfloat16(v.z);
    __nv_bfloat16 h3 = __float2bfloat16(v.w);
    __nv_bfloat16 l0 = __float2bfloat16(v.x - __bfloat162float(h0));
    __nv_bfloat16 l1 = __float2bfloat16(v.y - __bfloat162float(h1));
    __nv_bfloat16 l2 = __float2bfloat16(v.z - __bfloat162float(h2));
    __nv_bfloat16 l3 = __float2bfloat16(v.w - __bfloat162float(h3));

    __nv_bfloat162* ph = reinterpret_cast<__nv_bfloat162*>(g_xhi);
    __nv_bfloat162* pl = reinterpret_cast<__nv_bfloat162*>(g_xlo);
    ph[2 * i]     = __nv_bfloat162(h0, h1);
    ph[2 * i + 1] = __nv_bfloat162(h2, h3);
    pl[2 * i]     = __nv_bfloat162(l0, l1);
    pl[2 * i + 1] = __nv_bfloat162(l2, l3);
}

// ---------------------------------------------------------------------------
// Kernel 2: build H^T in bf16 hi/lo.
//   H[r, n] = sum_i rule[i, a, k] * W[i, c, p],  r=a*512+c, n=k*2048+p
// ---------------------------------------------------------------------------
__global__ __launch_bounds__(256) void build_Ht_kernel(
    const float* __restrict__ rule,   // (4,4,4)
    const float* __restrict__ W)      // (4,512,2048)
{
    __shared__ float hs[64][65];

    const int n0 = blockIdx.x * 64;   // over OUT_FEATS
    const int r0 = blockIdx.y * 64;   // over IN_FEATS
    const int a = r0 >> 9;
    const int k = n0 >> 11;

    const float s0 = rule[0 * 16 + a * 4 + k];
    const float s1 = rule[1 * 16 + a * 4 + k];
    const float s2 = rule[2 * 16 + a * 4 + k];
    const float s3 = rule[3 * 16 + a * 4 + k];

    {
        const int nl = threadIdx.x & 63;
        const int rg = threadIdx.x >> 6;    // 0..3
        const int p = (n0 & 2047) + nl;
        const int cbase = (r0 & 511);
#pragma unroll
        for (int j = 0; j < 16; j++) {
            const int rl = rg * 16 + j;
            const int c = cbase + rl;
            float acc = s0 * W[(size_t)(0 * IN_PER + c) * OUT_PER + p]
                      + s1 * W[(size_t)(1 * IN_PER + c) * OUT_PER + p]
                      + s2 * W[(size_t)(2 * IN_PER + c) * OUT_PER + p]
                      + s3 * W[(size_t)(3 * IN_PER + c) * OUT_PER + p];
            hs[rl][nl] = acc;
        }
    }
    __syncthreads();
    {
        const int rl = threadIdx.x & 63;
        const int ng = threadIdx.x >> 6;
#pragma unroll
        for (int j = 0; j < 16; j++) {
            const int nn = ng * 16 + j;
            const float v = hs[rl][nn];
            const __nv_bfloat16 hi = __float2bfloat16(v);
            const __nv_bfloat16 lo = __float2bfloat16(v - __bfloat162float(hi));
            const size_t o = (size_t)(n0 + nn) * IN_FEATS + r0 + rl;
            g_Hthi[o] = hi;
            g_Htlo[o] = lo;
        }
    }
}

// ---------------------------------------------------------------------------
// Kernel 3: HMMA GEMM (mma.sync bf16), y = x @ H + b, double-bf16 3-product.
//   CTA tile 128x256, KC=32, 3-stage cp.async pipeline.
//   smem row layout (128B/row, SW128 swizzle): [hi k0..31 | lo k0..31]
// ---------------------------------------------------------------------------
#define BM 128
#define BN 256
#define KC 32
#define NSTAGE 3
#define NCHUNK (IN_FEATS / KC)              // 64
#define SM_B_OFF (BM * 128)                 // 16 KB: B region after A region
#define STAGE_BYTES ((BM + BN) * 128)       // 48 KB
#define SMEM_TOTAL_GEMM (NSTAGE * STAGE_BYTES)  // 144 KB

__global__ __launch_bounds__(256, 1) void phm_mma_kernel(
    const float* __restrict__ bias,
    float* __restrict__ C)
{
    extern __shared__ char smem[];
    const uint32_t sbase = smem_to_u32(smem);
    const int tid = threadIdx.x;
    const int lid = tid & 31;
    const int wid = tid >> 5;
    const int warp_m = wid & 1;       // 2 warps over M (64 rows each)
    const int warp_n = wid >> 1;      // 4 warps over N (64 cols each)

    const int mrow0 = blockIdx.x * BM;
    const int ncol0 = blockIdx.y * BN;

    float acc[4][8][4];
#pragma unroll
    for (int i = 0; i < 4; i++)
#pragma unroll
        for (int j = 0; j < 8; j++)
#pragma unroll
            for (int e = 0; e < 4; e++) acc[i][j][e] = 0.f;

    // ---- stage loader (A: 1024 16B chunks, B: 2048 16B chunks) ----
#define LOAD_STAGE(sptr, c) do {                                              \
    const int _kc0 = (c) * KC;                                                \
    _Pragma("unroll")                                                         \
    for (int _j = 0; _j < 4; _j++) {                                          \
        const int _q = tid + 256 * _j;                                        \
        const int _row = _q >> 3; const int _u = _q & 7;                      \
        const uint32_t _so = (sptr) +                                         \
            SMEM_SWIZZLE_128B((uint32_t)(_row * 128 + _u * 16));              \
        const __nv_bfloat16* _src = (_u < 4)                                  \
            ? (g_xhi + (size_t)(mrow0 + _row) * IN_FEATS + _kc0 + _u * 8)     \
            : (g_xlo + (size_t)(mrow0 + _row) * IN_FEATS + _kc0 + (_u - 4) * 8); \
        CP_ASYNC16(_so, _src);                                                \
    }                                                                         \
    _Pragma("unroll")                                                         \
    for (int _j = 0; _j < 8; _j++) {                                          \
        const int _q = tid + 256 * _j;                                        \
        const int _row = _q >> 3; const int _u = _q & 7;                      \
        const uint32_t _so = (sptr) + SM_B_OFF +                              \
            SMEM_SWIZZLE_128B((uint32_t)(_row * 128 + _u * 16));              \
        const __nv_bfloat16* _src = (_u < 4)                                  \
            ? (g_Hthi + (size_t)(ncol0 + _row) * IN_FEATS + _kc0 + _u * 8)    \
            : (g_Htlo + (size_t)(ncol0 + _row) * IN_FEATS + _kc0 + (_u - 4) * 8); \
        CP_ASYNC16(_so, _src);                                                \
    }                                                                         \
    CP_ASYNC_COMMIT();                                                        \
} while (0)

    // Prologue: fill stages 0 and 1
    LOAD_STAGE(sbase + 0 * STAGE_BYTES, 0);
    LOAD_STAGE(sbase + 1 * STAGE_BYTES, 1);

    // Lane-constant fragment addressing pieces
    const int a_row_l = lid & 15;                         // + 16B col sel below
    const int a_k16   = (lid >> 4) * 16;
    const int b_row_l = ((lid >> 4) << 3) + (lid & 7);
    const int b_k16   = ((lid >> 3) & 1) * 16;

    int sidx = 0;
    for (int c = 0; c < NCHUNK; c++) {
        if (c + 1 < NCHUNK) {
            asm volatile("cp.async.wait_group 1;" ::: "memory");
        } else {
            asm volatile("cp.async.wait_group 0;" ::: "memory");
        }
        __syncthreads();

        if (c + 2 < NCHUNK) {
            const int ns = (sidx + 2 >= NSTAGE) ? (sidx + 2 - NSTAGE) : (sidx + 2);
            LOAD_STAGE(sbase + ns * STAGE_BYTES, c + 2);
        }

        const uint32_t abase = sbase + sidx * STAGE_BYTES;
        const uint32_t bbase = abase + SM_B_OFF;

#pragma unroll
        for (int ks = 0; ks < 2; ks++) {   // two K=16 steps per KC=32 chunk
            uint32_t ah[4][4], al[4][4], bh[4][4], bl[4][4];

#pragma unroll
            for (int mt = 0; mt < 4; mt++) {
                const int row = warp_m * 64 + mt * 16 + a_row_l;
                const uint32_t byte = (uint32_t)(row * 128 + ks * 32 + a_k16);
                const uint32_t hi = abase + SMEM_SWIZZLE_128B(byte);
                const uint32_t lo = abase + SMEM_SWIZZLE_128B(byte + 64);
                LDSM_X4(ah[mt][0], ah[mt][1], ah[mt][2], ah[mt][3], hi);
                LDSM_X4(al[mt][0], al[mt][1], al[mt][2], al[mt][3], lo);
            }
#pragma unroll
            for (int ng = 0; ng < 4; ng++) {
                const int row = warp_n * 64 + ng * 16 + b_row_l;
                const uint32_t byte = (uint32_t)(row * 128 + ks * 32 + b_k16);
                const uint32_t hi = bbase + SMEM_SWIZZLE_128B(byte);
                const uint32_t lo = bbase + SMEM_SWIZZLE_128B(byte + 64);
                LDSM_X4(bh[ng][0], bh[ng][1], bh[ng][2], bh[ng][3], hi);
                LDSM_X4(bl[ng][0], bl[ng][1], bl[ng][2], bl[ng][3], lo);
            }

#pragma unroll
            for (int mt = 0; mt < 4; mt++) {
#pragma unroll
                for (int ng = 0; ng < 4; ng++) {
#pragma unroll
                    for (int h = 0; h < 2; h++) {
                        float* d = acc[mt][ng * 2 + h];
                        // hi*hi + hi*lo + lo*hi (lo*lo dropped, ~2^-18)
                        MMA_BF16(d, ah[mt], bh[ng][2 * h], bh[ng][2 * h + 1]);
                        MMA_BF16(d, ah[mt], bl[ng][2 * h], bl[ng][2 * h + 1]);
                        MMA_BF16(d, al[mt], bh[ng][2 * h], bh[ng][2 * h + 1]);
                    }
                }
            }
        }
        __syncthreads();
        sidx = (sidx + 1 == NSTAGE) ? 0 : sidx + 1;
    }

    // ---- Epilogue: bias + store (float2, coalesced per quad) ----
    const int qrow = lid >> 2;            // 0..7
    const int qcol = (lid & 3) * 2;       // 0,2,4,6
#pragma unroll
    for (int mt = 0; mt < 4; mt++) {
        const int r0 = mrow0 + warp_m * 64 + mt * 16 + qrow;
#pragma unroll
        for (int nb = 0; nb < 8; nb++) {
            const int col = ncol0 + warp_n * 64 + nb * 8 + qcol;
            const float2 bb = *reinterpret_cast<const float2*>(&bias[col]);
            float2 o0, o1;
            o0.x = acc[mt][nb][0] + bb.x;
            o0.y = acc[mt][nb][1] + bb.y;
            o1.x = acc[mt][nb][2] + bb.x;
            o1.y = acc[mt][nb][3] + bb.y;
            *reinterpret_cast<float2*>(&C[(size_t)r0 * OUT_FEATS + col]) = o0;
            *reinterpret_cast<float2*>(&C[(size_t)(r0 + 8) * OUT_FEATS + col]) = o1;
        }
    }
#undef LOAD_STAGE
}

// ---------------------------------------------------------------------------
// Launch: inputs per metadata order: x, phm_rule, W, b. Output float32.
// ---------------------------------------------------------------------------
extern "C" void kernel_launch(void* const* d_in, const int* in_sizes, int n_in,
                              void* d_out, int out_size) {
    const float* x    = (const float*)d_in[0];
    const float* rule = (const float*)d_in[1];
    const float* W    = (const float*)d_in[2];
    const float* b    = (const float*)d_in[3];
    float* y = (float*)d_out;
    (void)in_sizes; (void)n_in; (void)out_size;

    cudaFuncSetAttribute(phm_mma_kernel,
                         cudaFuncAttributeMaxDynamicSharedMemorySize,
                         SMEM_TOTAL_GEMM);

    // 1) split x into bf16 hi/lo
    {
        const int total4 = (TOKENS * IN_FEATS) / 4;
        split_x_kernel<<<total4 / 256, 256>>>(x);
    }
    // 2) build H^T bf16 hi/lo
    {
        dim3 grid(OUT_FEATS / 64, IN_FEATS / 64);   // (128, 32)
        build_Ht_kernel<<<grid, 256>>>(rule, W);
    }
    // 3) HMMA GEMM + bias.  blockIdx.x = M (fast) -> wave shares the N tile's
    //    B data in L2; A streams through.
    {
        dim3 grid(TOKENS / BM, OUT_FEATS / BN);     // (64, 32)
        phm_mma_kernel<<<grid, 256, SMEM_TOTAL_GEMM>>>(b, y);
    }
}